// round 15
// baseline (speedup 1.0000x reference)
#include <cuda_runtime.h>
#include <cuda_fp16.h>
#include <cstdint>
typedef uint32_t u32;

#define TT 64
#define BB 128
#define HH 256
#define G4H 1024
#define NBLK 128
#define NTHR 256

// fragment-major state arrays: unit (kt,row) = 32B, half order within unit:
// [k(2q),k(2q+1),k(2q+8),k(2q+9)] for q=0..3.
__device__ uint4 g_xF4[TT*16*BB*2];      // x, converted+permuted once
__device__ uint4 g_h0nF4[2][16*BB*2];    // fresh layer0 hidden (layer1 input)
__device__ uint4 g_h0sF4[2][16*BB*2];    // layer0 carried state
__device__ uint4 g_h1sF4[2][16*BB*2];    // layer1 carried state
__device__ unsigned g_flags[NBLK];       // flag idx == bid; 32/group = one 128B line
__device__ unsigned g_ctr0, g_gen0;      // init barrier only (monotonic)

__device__ __forceinline__ float sigf(float v){ return 1.0f/(1.0f+__expf(-v)); }

__device__ __forceinline__ unsigned ldacq(const unsigned* p){
  unsigned v; asm volatile("ld.global.acquire.gpu.u32 %0, [%1];" : "=r"(v) : "l"(p) : "memory");
  return v;
}
__device__ __forceinline__ void strel(unsigned* p, unsigned v){
  asm volatile("st.global.release.gpu.u32 [%0], %1;" :: "l"(p), "r"(v) : "memory");
}

// m16n8k16 fp16 mma, fp32 accum
__device__ __forceinline__ void hmma(float* d, u32 a0, u32 a1, u32 a2, u32 a3, uint2 b){
  asm volatile("mma.sync.aligned.m16n8k16.row.col.f32.f16.f16.f32 "
    "{%0,%1,%2,%3}, {%4,%5,%6,%7}, {%8,%9}, {%0,%1,%2,%3};"
    : "+f"(d[0]),"+f"(d[1]),"+f"(d[2]),"+f"(d[3])
    : "r"(a0),"r"(a1),"r"(a2),"r"(a3), "r"(b.x),"r"(b.y));
}

// init-only central barrier (monotonic gen, replay-safe)
__device__ __forceinline__ void init_arrive_and_wait(unsigned base){
  __syncthreads();
  if (threadIdx.x == 0){
    __threadfence();
    unsigned old = atomicAdd(&g_ctr0, 1u);
    if (old == (unsigned)(NBLK-1)){
      *(volatile unsigned*)&g_ctr0 = 0u;
      __threadfence();
      atomicAdd(&g_gen0, 1u);
    }
    while (*(volatile unsigned*)&g_gen0 - base < 1u){ }
    __threadfence();
  }
  __syncthreads();
}

// PER-WARP wait: all 32 flags of group gb >= tgt (one 128B line, lane-parallel)
__device__ __forceinline__ void wait_flags_w(int gb, unsigned tgt){
  const unsigned* p = &g_flags[gb + (threadIdx.x & 31)];
  unsigned v = ldacq(p);
  while (!__all_sync(0xffffffffu, v >= tgt)) v = ldacq(p);
}

// half-position of INTRA-TILE k-index i (0..15 ONLY) inside a 32B unit
__device__ __forceinline__ int fragoff(int i){
  return ((i & 7) >> 1)*4 + ((i >> 3) << 1) + (i & 1);
}

// one K-half (16 k-tiles) from fragment-major global; per kt per lane:
// 2 coalesced LDG.64 feeding 2 n-tiles; even/odd accumulator chains.
__device__ __forceinline__ void compute_frag(
    const uint2* __restrict__ F, const uint2* __restrict__ wfrag,
    int kbase, int b1q, int b2q, int lane,
    float* a0a, float* a0b, float* a1a, float* a1b)
{
  #pragma unroll
  for (int ktl = 0; ktl < 16; ktl++){
    uint2 va = __ldcg(F + ktl*512 + b1q);
    uint2 vb = __ldcg(F + ktl*512 + b2q);
    uint2 w0 = wfrag[(kbase+ktl)*32 + lane];
    uint2 w1 = wfrag[1024 + (kbase+ktl)*32 + lane];
    if (ktl & 1){ hmma(a0b, va.x, vb.x, va.y, vb.y, w0); hmma(a1b, va.x, vb.x, va.y, vb.y, w1); }
    else        { hmma(a0a, va.x, vb.x, va.y, vb.y, w0); hmma(a1a, va.x, vb.x, va.y, vb.y, w1); }
  }
}

__global__ void __launch_bounds__(NTHR, 1) stacklstm_h16(
    const float* __restrict__ x,   const int* __restrict__ ops,
    const float* __restrict__ Wih, const float* __restrict__ Whh,
    const float* __restrict__ bih, const float* __restrict__ bhh,
    float* __restrict__ out)
{
  __shared__ uint2 wfrag[2048];     // [nt*1024 + kt*32 + lane], 16 KB

  const int tid = threadIdx.x, bid = blockIdx.x;
  const int wr = tid >> 5, lane = tid & 31;
  const int layer = bid >> 6;
  const int j0 = (bid & 63) * 4;

  const int own_g = bid & ~63;           // own flag-group base
  const int l0_g  = own_g - 64;          // layer1's matching layer0 group
  const int l1_g  = own_g + 64;          // layer0's matching layer1 group
  // NOTE: groups are 64 blocks but flags are packed contiguous; poll covers
  // 32 of 64 per warp call — so poll BOTH halves.

  const float* Wi = Wih + layer*G4H*HH;
  const float* Wh = Whh + layer*G4H*HH;

  // ---- W fragment pack (once): [nt2][kt32][lane32] ----
  for (int idx = tid; idx < 2048; idx += NTHR){
    int ln = idx & 31;
    int kt = (idx >> 5) & 31;
    int nt = idx >> 10;
    int n  = nt*8 + (ln >> 2);
    int wrow = (n >> 2)*HH + j0 + (n & 3);
    int k0 = kt*16 + (ln & 3)*2;
    const float* sw = (kt < 16) ? (Wi + wrow*HH + k0) : (Wh + wrow*HH + k0 - HH);
    __half2 p0 = __halves2half2(__float2half_rn(__ldg(sw)),   __float2half_rn(__ldg(sw+1)));
    __half2 p1 = __halves2half2(__float2half_rn(__ldg(sw+8)), __float2half_rn(__ldg(sw+9)));
    wfrag[idx] = make_uint2(*(u32*)&p0, *(u32*)&p1);
  }

  // per-thread EW constants (R6/R13 structure)
  const int q  = lane & 3;
  const int jj = (q >> 1) | ((q & 1) << 1);
  const int b1 = wr*16 + (lane >> 2);
  float biasv[4];
  #pragma unroll
  for (int g = 0; g < 4; g++){
    int wrow = g*HH + j0 + jj;
    biasv[g] = __ldg(bih + layer*G4H + wrow) + __ldg(bhh + layer*G4H + wrow);
  }

  // ---- x -> fragment-major fp16 (once) ----
  #pragma unroll 1
  for (int u0 = 0; u0 < 4; u0++){
    int u = u0*(NBLK*NTHR) + bid*NTHR + tid;
    int t   = u >> 11;
    int kt  = (u >> 7) & 15;
    int row = u & 127;
    const float* sp = x + (t*BB + row)*HH + kt*16;
    float4 f0 = __ldg((const float4*)sp);
    float4 f1 = __ldg((const float4*)(sp+4));
    float4 f2 = __ldg((const float4*)(sp+8));
    float4 f3 = __ldg((const float4*)(sp+12));
    __half2 d0 = __halves2half2(__float2half_rn(f0.x), __float2half_rn(f0.y));
    __half2 d1 = __halves2half2(__float2half_rn(f2.x), __float2half_rn(f2.y));
    __half2 d2 = __halves2half2(__float2half_rn(f0.z), __float2half_rn(f0.w));
    __half2 d3 = __halves2half2(__float2half_rn(f2.z), __float2half_rn(f2.w));
    __half2 d4 = __halves2half2(__float2half_rn(f1.x), __float2half_rn(f1.y));
    __half2 d5 = __halves2half2(__float2half_rn(f3.x), __float2half_rn(f3.y));
    __half2 d6 = __halves2half2(__float2half_rn(f1.z), __float2half_rn(f1.w));
    __half2 d7 = __halves2half2(__float2half_rn(f3.z), __float2half_rn(f3.w));
    uint4* dst = g_xF4 + (size_t)((t*16 + kt)*128 + row)*2;
    dst[0] = make_uint4(*(u32*)&d0, *(u32*)&d1, *(u32*)&d2, *(u32*)&d3);
    dst[1] = make_uint4(*(u32*)&d4, *(u32*)&d5, *(u32*)&d6, *(u32*)&d7);
  }
  // zero parity-0 state frags + own flag
  { int idx = bid*NTHR + tid;
    if (idx < 16*BB*2){
      g_h0sF4[0][idx] = make_uint4(0,0,0,0);
      g_h1sF4[0][idx] = make_uint4(0,0,0,0);
    } }
  if (tid == 0) g_flags[bid] = 0u;

  unsigned base0 = 0;
  if (tid == 0) base0 = *(volatile unsigned*)&g_gen0;
  init_arrive_and_wait(base0);   // zeros + x frags + flags visible after

  float c0 = 0.f, c1 = 0.f, hk0 = 0.f, hk1 = 0.f;
  const int b1q = b1*4 + q, b2q = (b1+8)*4 + q;
  const int ktv = j0 >> 4;
  const int fo  = fragoff((j0 + jj) & 15);

  for (int t = 0; t < TT; t++){
    float a0a[4]={0,0,0,0}, a0b[4]={0,0,0,0};
    float a1a[4]={0,0,0,0}, a1b[4]={0,0,0,0};

    if (layer == 0){
      // x half: no dependency — compute before any wait
      compute_frag((const uint2*)(g_xF4 + (size_t)t*16*128*2), wfrag, 0,
                   b1q, b2q, lane, a0a, a0b, a1a, a1b);
      if (t >= 1){ wait_flags_w(own_g, (unsigned)t); wait_flags_w(own_g+32, (unsigned)t); }
      compute_frag((const uint2*)g_h0sF4[t&1], wfrag, 16,
                   b1q, b2q, lane, a0a, a0b, a1a, a1b);
      // h0n buffer free: layer1 done t-2 (hidden under the h0s GEMM above)
      if (t >= 2){ wait_flags_w(l1_g, (unsigned)(t-1)); wait_flags_w(l1_g+32, (unsigned)(t-1)); }
    } else {
      if (t >= 1){ wait_flags_w(own_g, (unsigned)t); wait_flags_w(own_g+32, (unsigned)t); }
      compute_frag((const uint2*)g_h1sF4[t&1], wfrag, 16,
                   b1q, b2q, lane, a0a, a0b, a1a, a1b);
      wait_flags_w(l0_g, (unsigned)(t+1)); wait_flags_w(l0_g+32, (unsigned)(t+1));
      compute_frag((const uint2*)g_h0nF4[t&1], wfrag, 0,
                   b1q, b2q, lane, a0a, a0b, a1a, a1b);
    }

    float acc0[4], acc1[4];
    #pragma unroll
    for (int i = 0; i < 4; i++){ acc0[i] = a0a[i]+a0b[i]; acc1[i] = a1a[i]+a1b[i]; }

    // ---- in-register gate exchange + LSTM elementwise ----
    {
      float s0 = __shfl_xor_sync(0xffffffffu, (q < 2) ? acc0[1] : acc0[0], 2);
      float s1 = __shfl_xor_sync(0xffffffffu, (q < 2) ? acc0[3] : acc0[2], 2);
      float s2 = __shfl_xor_sync(0xffffffffu, (q < 2) ? acc1[1] : acc1[0], 2);
      float s3 = __shfl_xor_sync(0xffffffffu, (q < 2) ? acc1[3] : acc1[2], 2);
      float gi0, gf0, gg0, go0, gi1, gf1, gg1, go1;
      if (q < 2){
        gi0 = acc0[0]; gf0 = s0; gg0 = acc1[0]; go0 = s2;
        gi1 = acc0[2]; gf1 = s1; gg1 = acc1[2]; go1 = s3;
      } else {
        gi0 = s0; gf0 = acc0[1]; gg0 = s2; go0 = acc1[1];
        gi1 = s1; gf1 = acc0[3]; gg1 = s3; go1 = acc1[3];
      }
      gi0 += biasv[0]; gf0 += biasv[1]; gg0 += biasv[2]; go0 += biasv[3];
      gi1 += biasv[0]; gf1 += biasv[1]; gg1 += biasv[2]; go1 += biasv[3];

      const int op0 = __ldg(ops + t*BB + b1);
      const int op1 = __ldg(ops + t*BB + b1 + 8);
      float cn0 = sigf(gf0)*c0 + sigf(gi0)*tanhf(gg0);
      float hn0 = sigf(go0)*tanhf(cn0);
      float cn1 = sigf(gf1)*c1 + sigf(gi1)*tanhf(gg1);
      float hn1 = sigf(go1)*tanhf(cn1);
      if (op0){ c0 = cn0; hk0 = hn0; }
      if (op1){ c1 = cn1; hk1 = hn1; }

      const int u0h = (ktv*128 + b1)*16 + fo;
      const int u1h = (ktv*128 + b1 + 8)*16 + fo;
      if (layer == 0){
        __half* fresh = (__half*)g_h0nF4[t&1];
        __half* keep  = (__half*)g_h0sF4[(t+1)&1];
        fresh[u0h] = __float2half_rn(hn0); fresh[u1h] = __float2half_rn(hn1);
        keep[u0h]  = __float2half_rn(hk0); keep[u1h]  = __float2half_rn(hk1);
      } else {
        float* fresh = out + t*BB*HH;
        __half* keep = (__half*)g_h1sF4[(t+1)&1];
        fresh[b1*HH + j0 + jj]     = hn0;
        fresh[(b1+8)*HH + j0 + jj] = hn1;
        keep[u0h]  = __float2half_rn(hk0); keep[u1h]  = __float2half_rn(hk1);
      }
    }

    __syncthreads();                               // all warps' EW stores issued
    if (tid == 0) strel(&g_flags[bid], (unsigned)(t+1));
  }
}

extern "C" void kernel_launch(void* const* d_in, const int* in_sizes, int n_in,
                              void* d_out, int out_size)
{
  const float* x   = (const float*)d_in[0];
  const int*   ops = (const int*)  d_in[1];
  const float* Wih = (const float*)d_in[2];
  const float* Whh = (const float*)d_in[3];
  const float* bih = (const float*)d_in[4];
  const float* bhh = (const float*)d_in[5];
  float* out = (float*)d_out;
  stacklstm_h16<<<NBLK, NTHR>>>(x, ops, Wih, Whh, bih, bhh, out);
}

// round 16
// speedup vs baseline: 1.4228x; 1.4228x over previous
#include <cuda_runtime.h>
#include <cuda_fp16.h>
#include <cstdint>
typedef uint32_t u32;

#define TT 64
#define BB 128
#define HH 256
#define G4H 1024
#define NBLK 128
#define NTHR 256

// fragment-major state arrays: unit (kt,row) = 32B, half order within unit:
// [k(2q),k(2q+1),k(2q+8),k(2q+9)] for q=0..3.
__device__ uint4 g_xF4[TT*16*BB*2];      // x, converted+permuted once
__device__ uint4 g_h0nF4[2][16*BB*2];    // fresh layer0 hidden (layer1 input)
__device__ uint4 g_h0sF4[2][16*BB*2];    // layer0 carried state
__device__ uint4 g_h1sF4[2][16*BB*2];    // layer1 carried state
__device__ unsigned g_flags[NBLK];       // PACKED: group of 32 = one 128B line
__device__ unsigned g_ctr0, g_gen0;      // init barrier only (monotonic)

__device__ __forceinline__ float sigf(float v){ return 1.0f/(1.0f+__expf(-v)); }

__device__ __forceinline__ unsigned ldacq(const unsigned* p){
  unsigned v; asm volatile("ld.global.acquire.gpu.u32 %0, [%1];" : "=r"(v) : "l"(p) : "memory");
  return v;
}
__device__ __forceinline__ void strel(unsigned* p, unsigned v){
  asm volatile("st.global.release.gpu.u32 [%0], %1;" :: "l"(p), "r"(v) : "memory");
}

// m16n8k16 fp16 mma, fp32 accum
__device__ __forceinline__ void hmma(float* d, u32 a0, u32 a1, u32 a2, u32 a3, uint2 b){
  asm volatile("mma.sync.aligned.m16n8k16.row.col.f32.f16.f16.f32 "
    "{%0,%1,%2,%3}, {%4,%5,%6,%7}, {%8,%9}, {%0,%1,%2,%3};"
    : "+f"(d[0]),"+f"(d[1]),"+f"(d[2]),"+f"(d[3])
    : "r"(a0),"r"(a1),"r"(a2),"r"(a3), "r"(b.x),"r"(b.y));
}

// init-only central barrier (monotonic gen, replay-safe)
__device__ __forceinline__ void init_arrive_and_wait(unsigned base){
  __syncthreads();
  if (threadIdx.x == 0){
    __threadfence();
    unsigned old = atomicAdd(&g_ctr0, 1u);
    if (old == (unsigned)(NBLK-1)){
      *(volatile unsigned*)&g_ctr0 = 0u;
      __threadfence();
      atomicAdd(&g_gen0, 1u);
    }
    while (*(volatile unsigned*)&g_gen0 - base < 1u){ }
    __threadfence();
  }
  __syncthreads();
}

// warp 0 polls the 32 PACKED flags of group gbase (one 128B line)
__device__ __forceinline__ void wait_flags(int gbase, unsigned tgt){
  if (threadIdx.x < 32){
    const unsigned* p = &g_flags[gbase + threadIdx.x];
    unsigned v = ldacq(p);
    while (!__all_sync(0xffffffffu, v >= tgt)) v = ldacq(p);
  }
}

// half-position of INTRA-TILE k-index i (0..15 ONLY) inside a 32B unit
__device__ __forceinline__ int fragoff(int i){
  return ((i & 7) >> 1)*4 + ((i >> 3) << 1) + (i & 1);
}

// one 256-k source (16 k-tiles) from fragment-major global; per kt per lane:
// 2 coalesced LDG.64. wf = this warp-col's fragment table; kbase selects W half.
__device__ __forceinline__ void compute_frag(
    const uint2* __restrict__ F, const uint2* __restrict__ wf,
    int kbase, int b1q, int b2q, int lane,
    float* a0a, float* a0b, float* a1a, float* a1b)
{
  #pragma unroll
  for (int ktl = 0; ktl < 16; ktl++){
    int kt = kbase + ktl;
    uint2 va = __ldcg(F + ktl*512 + b1q);
    uint2 vb = __ldcg(F + ktl*512 + b2q);
    uint2 w0 = wf[kt*32 + lane];
    uint2 w1 = wf[1024 + kt*32 + lane];
    if (ktl & 1){ hmma(a0b, va.x, vb.x, va.y, vb.y, w0); hmma(a1b, va.x, vb.x, va.y, vb.y, w1); }
    else        { hmma(a0a, va.x, vb.x, va.y, vb.y, w0); hmma(a1a, va.x, vb.x, va.y, vb.y, w1); }
  }
}

__global__ void __launch_bounds__(NTHR, 1) stacklstm_h16(
    const float* __restrict__ x,   const int* __restrict__ ops,
    const float* __restrict__ Wih, const float* __restrict__ Whh,
    const float* __restrict__ bih, const float* __restrict__ bhh,
    float* __restrict__ out)
{
  __shared__ uint2 wfrag[4096];     // [wc2][nt2][kt32][lane32], 32 KB

  const int tid = threadIdx.x, bid = blockIdx.x;
  const int wid = tid >> 5, lane = tid & 31;
  const int layer = bid >> 6;            // 0 / 1
  const int half  = (bid >> 5) & 1;      // batch half
  const int cg    = bid & 31;            // 8 j's per block
  const int j0    = cg * 8;
  const int b0    = half * 64;
  const int wr2   = wid >> 1;            // 4 row groups of 16
  const int wc    = wid & 1;             // 2 col sub-blocks of 4 j's

  const int own_g = bid & ~31;           // own flag-group base (block idx)
  const int l0_g  = own_g - 64;          // for layer1: matching layer0 group
  const int l1_g  = own_g + 64;          // for layer0: matching layer1 group

  const float* Wi = Wih + layer*G4H*HH;
  const float* Wh = Whh + layer*G4H*HH;

  // ---- W fragment pack (once): [wc2][nt2][kt32][lane32] ----
  for (int idx = tid; idx < 4096; idx += NTHR){
    int ln = idx & 31;
    int kt = (idx >> 5) & 31;
    int nt = (idx >> 10) & 1;
    int wc2 = idx >> 11;
    int n  = nt*8 + (ln >> 2);                       // sub-block col 0..15
    int wrow = (n >> 2)*HH + j0 + wc2*4 + (n & 3);   // gate = n>>2, jl = n&3
    int k0 = kt*16 + (ln & 3)*2;
    const float* sw = (kt < 16) ? (Wi + wrow*HH + k0) : (Wh + wrow*HH + k0 - HH);
    __half2 p0 = __halves2half2(__float2half_rn(__ldg(sw)),   __float2half_rn(__ldg(sw+1)));
    __half2 p1 = __halves2half2(__float2half_rn(__ldg(sw+8)), __float2half_rn(__ldg(sw+9)));
    wfrag[idx] = make_uint2(*(u32*)&p0, *(u32*)&p1);
  }

  // per-thread EW constants (R6 sub-block structure, j base = j0 + wc*4)
  const int q  = lane & 3;
  const int jj = (q >> 1) | ((q & 1) << 1);
  const int jg = j0 + wc*4 + jj;                 // global j of this thread
  const int b1 = b0 + wr2*16 + (lane >> 2);      // rows b1, b1+8
  float biasv[4];
  #pragma unroll
  for (int g = 0; g < 4; g++){
    int wrow = g*HH + jg;
    biasv[g] = __ldg(bih + layer*G4H + wrow) + __ldg(bhh + layer*G4H + wrow);
  }

  // ---- x -> fragment-major fp16 (once) ----
  #pragma unroll 1
  for (int u0 = 0; u0 < 4; u0++){
    int u = u0*(NBLK*NTHR) + bid*NTHR + tid;
    int t   = u >> 11;
    int kt  = (u >> 7) & 15;
    int row = u & 127;
    const float* sp = x + (t*BB + row)*HH + kt*16;
    float4 f0 = __ldg((const float4*)sp);
    float4 f1 = __ldg((const float4*)(sp+4));
    float4 f2 = __ldg((const float4*)(sp+8));
    float4 f3 = __ldg((const float4*)(sp+12));
    __half2 d0 = __halves2half2(__float2half_rn(f0.x), __float2half_rn(f0.y));
    __half2 d1 = __halves2half2(__float2half_rn(f2.x), __float2half_rn(f2.y));
    __half2 d2 = __halves2half2(__float2half_rn(f0.z), __float2half_rn(f0.w));
    __half2 d3 = __halves2half2(__float2half_rn(f2.z), __float2half_rn(f2.w));
    __half2 d4 = __halves2half2(__float2half_rn(f1.x), __float2half_rn(f1.y));
    __half2 d5 = __halves2half2(__float2half_rn(f3.x), __float2half_rn(f3.y));
    __half2 d6 = __halves2half2(__float2half_rn(f1.z), __float2half_rn(f1.w));
    __half2 d7 = __halves2half2(__float2half_rn(f3.z), __float2half_rn(f3.w));
    uint4* dst = g_xF4 + (size_t)((t*16 + kt)*128 + row)*2;
    dst[0] = make_uint4(*(u32*)&d0, *(u32*)&d1, *(u32*)&d2, *(u32*)&d3);
    dst[1] = make_uint4(*(u32*)&d4, *(u32*)&d5, *(u32*)&d6, *(u32*)&d7);
  }
  // zero parity-0 state frags + own flag
  { int idx = bid*NTHR + tid;
    if (idx < 16*BB*2){
      g_h0sF4[0][idx] = make_uint4(0,0,0,0);
      g_h1sF4[0][idx] = make_uint4(0,0,0,0);
    } }
  if (tid == 0) g_flags[bid] = 0u;

  unsigned base0 = 0;
  if (tid == 0) base0 = *(volatile unsigned*)&g_gen0;
  init_arrive_and_wait(base0);   // zeros + x frags + flags visible after

  float c0 = 0.f, c1 = 0.f, hk0 = 0.f, hk1 = 0.f;
  const int b1q = b1*4 + q, b2q = (b1+8)*4 + q;
  const int ktv = jg >> 4;
  const int fo  = fragoff(jg & 15);
  const uint2* wf = wfrag + wc*2048;

  for (int t = 0; t < TT; t++){
    float a0a[4]={0,0,0,0}, a0b[4]={0,0,0,0};
    float a1a[4]={0,0,0,0}, a1b[4]={0,0,0,0};

    if (layer == 0){
      // x half: no dependency — compute before any wait
      compute_frag((const uint2*)(g_xF4 + (size_t)t*16*128*2), wf, 0,
                   b1q, b2q, lane, a0a, a0b, a1a, a1b);
      if (t >= 1) wait_flags(own_g, (unsigned)t);        // own done t-1 (h0s)
      if (t >= 2) wait_flags(l1_g, (unsigned)(t-1));     // L1 done t-2 (h0n free)
      __syncthreads();
      compute_frag((const uint2*)g_h0sF4[t&1], wf, 16,
                   b1q, b2q, lane, a0a, a0b, a1a, a1b);
    } else {
      if (t >= 1) wait_flags(own_g, (unsigned)t);        // own done t-1 (h1s)
      __syncthreads();
      compute_frag((const uint2*)g_h1sF4[t&1], wf, 16,
                   b1q, b2q, lane, a0a, a0b, a1a, a1b);
      wait_flags(l0_g, (unsigned)(t+1));                 // L0 done t (h0n ready)
      __syncthreads();
      compute_frag((const uint2*)g_h0nF4[t&1], wf, 0,
                   b1q, b2q, lane, a0a, a0b, a1a, a1b);
    }

    float acc0[4], acc1[4];
    #pragma unroll
    for (int i = 0; i < 4; i++){ acc0[i] = a0a[i]+a0b[i]; acc1[i] = a1a[i]+a1b[i]; }

    // ---- in-register gate exchange + LSTM elementwise (R6 structure) ----
    {
      float s0 = __shfl_xor_sync(0xffffffffu, (q < 2) ? acc0[1] : acc0[0], 2);
      float s1 = __shfl_xor_sync(0xffffffffu, (q < 2) ? acc0[3] : acc0[2], 2);
      float s2 = __shfl_xor_sync(0xffffffffu, (q < 2) ? acc1[1] : acc1[0], 2);
      float s3 = __shfl_xor_sync(0xffffffffu, (q < 2) ? acc1[3] : acc1[2], 2);
      float gi0, gf0, gg0, go0, gi1, gf1, gg1, go1;
      if (q < 2){
        gi0 = acc0[0]; gf0 = s0; gg0 = acc1[0]; go0 = s2;
        gi1 = acc0[2]; gf1 = s1; gg1 = acc1[2]; go1 = s3;
      } else {
        gi0 = s0; gf0 = acc0[1]; gg0 = s2; go0 = acc1[1];
        gi1 = s1; gf1 = acc0[3]; gg1 = s3; go1 = acc1[3];
      }
      gi0 += biasv[0]; gf0 += biasv[1]; gg0 += biasv[2]; go0 += biasv[3];
      gi1 += biasv[0]; gf1 += biasv[1]; gg1 += biasv[2]; go1 += biasv[3];

      const int op0 = __ldg(ops + t*BB + b1);
      const int op1 = __ldg(ops + t*BB + b1 + 8);
      float cn0 = sigf(gf0)*c0 + sigf(gi0)*tanhf(gg0);
      float hn0 = sigf(go0)*tanhf(cn0);
      float cn1 = sigf(gf1)*c1 + sigf(gi1)*tanhf(gg1);
      float hn1 = sigf(go1)*tanhf(cn1);
      if (op0){ c0 = cn0; hk0 = hn0; }
      if (op1){ c1 = cn1; hk1 = hn1; }

      const int u0h = (ktv*128 + b1)*16 + fo;
      const int u1h = (ktv*128 + b1 + 8)*16 + fo;
      if (layer == 0){
        __half* fresh = (__half*)g_h0nF4[t&1];
        __half* keep  = (__half*)g_h0sF4[(t+1)&1];
        fresh[u0h] = __float2half_rn(hn0); fresh[u1h] = __float2half_rn(hn1);
        keep[u0h]  = __float2half_rn(hk0); keep[u1h]  = __float2half_rn(hk1);
      } else {
        float* fresh = out + t*BB*HH;
        __half* keep = (__half*)g_h1sF4[(t+1)&1];
        fresh[b1*HH + jg]     = hn0;
        fresh[(b1+8)*HH + jg] = hn1;
        keep[u0h]  = __float2half_rn(hk0); keep[u1h]  = __float2half_rn(hk1);
      }
    }

    __syncthreads();                               // all EW stores issued
    if (tid == 0) strel(&g_flags[bid], (unsigned)(t+1));
  }
}

extern "C" void kernel_launch(void* const* d_in, const int* in_sizes, int n_in,
                              void* d_out, int out_size)
{
  const float* x   = (const float*)d_in[0];
  const int*   ops = (const int*)  d_in[1];
  const float* Wih = (const float*)d_in[2];
  const float* Whh = (const float*)d_in[3];
  const float* bih = (const float*)d_in[4];
  const float* bhh = (const float*)d_in[5];
  float* out = (float*)d_out;
  stacklstm_h16<<<NBLK, NTHR>>>(x, ops, Wih, Whh, bih, bhh, out);
}

// round 17
// speedup vs baseline: 2.5700x; 1.8063x over previous
#include <cuda_runtime.h>
#include <cuda_fp16.h>
#include <cstdint>
typedef uint32_t u32;

#define TT 64
#define BB 128
#define HH 256
#define G4H 1024
#define NBLK 256
#define NTHR 128

// fragment-major state arrays: unit (kt,row) = 32B, half order within unit:
// [k(2q),k(2q+1),k(2q+8),k(2q+9)] for q=0..3.
__device__ uint4 g_xF4[TT*16*BB*2];      // x, converted+permuted once
__device__ uint4 g_h0nF4[2][16*BB*2];    // fresh layer0 hidden (layer1 input)
__device__ uint4 g_h0sF4[2][16*BB*2];    // layer0 carried state
__device__ uint4 g_h1sF4[2][16*BB*2];    // layer1 carried state
__device__ unsigned g_flags[NBLK*64];    // per-block step flag, 256B stride (OWN line)
__device__ unsigned g_ctr0, g_gen0;      // init barrier only (monotonic)

__device__ __forceinline__ float sigf(float v){ return 1.0f/(1.0f+__expf(-v)); }

__device__ __forceinline__ unsigned ldacq(const unsigned* p){
  unsigned v; asm volatile("ld.global.acquire.gpu.u32 %0, [%1];" : "=r"(v) : "l"(p) : "memory");
  return v;
}
__device__ __forceinline__ void strel(unsigned* p, unsigned v){
  asm volatile("st.global.release.gpu.u32 [%0], %1;" :: "l"(p), "r"(v) : "memory");
}

// m16n8k16 fp16 mma, fp32 accum
__device__ __forceinline__ void hmma(float* d, u32 a0, u32 a1, u32 a2, u32 a3, uint2 b){
  asm volatile("mma.sync.aligned.m16n8k16.row.col.f32.f16.f16.f32 "
    "{%0,%1,%2,%3}, {%4,%5,%6,%7}, {%8,%9}, {%0,%1,%2,%3};"
    : "+f"(d[0]),"+f"(d[1]),"+f"(d[2]),"+f"(d[3])
    : "r"(a0),"r"(a1),"r"(a2),"r"(a3), "r"(b.x),"r"(b.y));
}

// init-only central barrier (monotonic gen, replay-safe)
__device__ __forceinline__ void init_arrive_and_wait(unsigned base){
  __syncthreads();
  if (threadIdx.x == 0){
    __threadfence();
    unsigned old = atomicAdd(&g_ctr0, 1u);
    if (old == (unsigned)(NBLK-1)){
      *(volatile unsigned*)&g_ctr0 = 0u;
      __threadfence();
      atomicAdd(&g_gen0, 1u);
    }
    while (*(volatile unsigned*)&g_gen0 - base < 1u){ }
    __threadfence();
  }
  __syncthreads();
}

// warp 0 polls the 32 strided flags of group gbase until all >= tgt
__device__ __forceinline__ void wait_flags(int gbase, unsigned tgt){
  if (threadIdx.x < 32){
    const unsigned* p = &g_flags[(gbase + threadIdx.x)*64];
    unsigned v = ldacq(p);
    while (!__all_sync(0xffffffffu, v >= tgt)) v = ldacq(p);
  }
}

// half-position of INTRA-TILE k-index i (0..15 ONLY) inside a 32B unit
__device__ __forceinline__ int fragoff(int i){
  return ((i & 7) >> 1)*4 + ((i >> 3) << 1) + (i & 1);
}

// one 256-k source (16 k-tiles) from fragment-major global; per kt per lane:
// 2 coalesced LDG.64. wf = this warp-col's fragment table; kbase selects W half.
__device__ __forceinline__ void compute_frag(
    const uint2* __restrict__ F, const uint2* __restrict__ wf,
    int kbase, int b1q, int b2q, int lane,
    float* a0a, float* a0b, float* a1a, float* a1b)
{
  #pragma unroll
  for (int ktl = 0; ktl < 16; ktl++){
    int kt = kbase + ktl;
    uint2 va = __ldcg(F + ktl*512 + b1q);
    uint2 vb = __ldcg(F + ktl*512 + b2q);
    uint2 w0 = wf[kt*32 + lane];
    uint2 w1 = wf[1024 + kt*32 + lane];
    if (ktl & 1){ hmma(a0b, va.x, vb.x, va.y, vb.y, w0); hmma(a1b, va.x, vb.x, va.y, vb.y, w1); }
    else        { hmma(a0a, va.x, vb.x, va.y, vb.y, w0); hmma(a1a, va.x, vb.x, va.y, vb.y, w1); }
  }
}

__global__ void __launch_bounds__(NTHR, 2) stacklstm_h16(
    const float* __restrict__ x,   const int* __restrict__ ops,
    const float* __restrict__ Wih, const float* __restrict__ Whh,
    const float* __restrict__ bih, const float* __restrict__ bhh,
    float* __restrict__ out)
{
  __shared__ uint2 wfrag[4096];     // [wc2][nt2][kt32][lane32], 32 KB

  const int tid = threadIdx.x, bid = blockIdx.x;
  const int wid = tid >> 5, lane = tid & 31;
  const int layer = bid >> 7;            // 0 / 1
  const int quart = (bid >> 5) & 3;      // batch quarter (32 rows)
  const int cg    = bid & 31;            // 8 j's per block
  const int j0    = cg * 8;
  const int b0    = quart * 32;
  const int wr2   = wid >> 1;            // 2 row groups of 16
  const int wc    = wid & 1;             // 2 col sub-blocks of 4 j's

  const int own_g = bid & ~31;           // own flag-group base (block idx)
  const int l0_g  = own_g - 128;         // layer1: matching layer0 group
  const int l1_g  = own_g + 128;         // layer0: matching layer1 group

  const float* Wi = Wih + layer*G4H*HH;
  const float* Wh = Whh + layer*G4H*HH;

  // ---- W fragment pack (once): [wc2][nt2][kt32][lane32] ----
  for (int idx = tid; idx < 4096; idx += NTHR){
    int ln = idx & 31;
    int kt = (idx >> 5) & 31;
    int nt = (idx >> 10) & 1;
    int wc2 = idx >> 11;
    int n  = nt*8 + (ln >> 2);                       // sub-block col 0..15
    int wrow = (n >> 2)*HH + j0 + wc2*4 + (n & 3);   // gate = n>>2, jl = n&3
    int k0 = kt*16 + (ln & 3)*2;
    const float* sw = (kt < 16) ? (Wi + wrow*HH + k0) : (Wh + wrow*HH + k0 - HH);
    __half2 p0 = __halves2half2(__float2half_rn(__ldg(sw)),   __float2half_rn(__ldg(sw+1)));
    __half2 p1 = __halves2half2(__float2half_rn(__ldg(sw+8)), __float2half_rn(__ldg(sw+9)));
    wfrag[idx] = make_uint2(*(u32*)&p0, *(u32*)&p1);
  }

  // per-thread EW constants (R6 sub-block structure, j base = j0 + wc*4)
  const int q  = lane & 3;
  const int jj = (q >> 1) | ((q & 1) << 1);
  const int jg = j0 + wc*4 + jj;                 // global j of this thread
  const int b1 = b0 + wr2*16 + (lane >> 2);      // rows b1, b1+8
  float biasv[4];
  #pragma unroll
  for (int g = 0; g < 4; g++){
    int wrow = g*HH + jg;
    biasv[g] = __ldg(bih + layer*G4H + wrow) + __ldg(bhh + layer*G4H + wrow);
  }

  // ---- x -> fragment-major fp16 (once) ----
  #pragma unroll 1
  for (int u0 = 0; u0 < 4; u0++){
    int u = u0*(NBLK*NTHR) + bid*NTHR + tid;   // 0..131071
    int t   = u >> 11;
    int kt  = (u >> 7) & 15;
    int row = u & 127;
    const float* sp = x + (t*BB + row)*HH + kt*16;
    float4 f0 = __ldg((const float4*)sp);
    float4 f1 = __ldg((const float4*)(sp+4));
    float4 f2 = __ldg((const float4*)(sp+8));
    float4 f3 = __ldg((const float4*)(sp+12));
    __half2 d0 = __halves2half2(__float2half_rn(f0.x), __float2half_rn(f0.y));
    __half2 d1 = __halves2half2(__float2half_rn(f2.x), __float2half_rn(f2.y));
    __half2 d2 = __halves2half2(__float2half_rn(f0.z), __float2half_rn(f0.w));
    __half2 d3 = __halves2half2(__float2half_rn(f2.z), __float2half_rn(f2.w));
    __half2 d4 = __halves2half2(__float2half_rn(f1.x), __float2half_rn(f1.y));
    __half2 d5 = __halves2half2(__float2half_rn(f3.x), __float2half_rn(f3.y));
    __half2 d6 = __halves2half2(__float2half_rn(f1.z), __float2half_rn(f1.w));
    __half2 d7 = __halves2half2(__float2half_rn(f3.z), __float2half_rn(f3.w));
    uint4* dst = g_xF4 + (size_t)((t*16 + kt)*128 + row)*2;
    dst[0] = make_uint4(*(u32*)&d0, *(u32*)&d1, *(u32*)&d2, *(u32*)&d3);
    dst[1] = make_uint4(*(u32*)&d4, *(u32*)&d5, *(u32*)&d6, *(u32*)&d7);
  }
  // zero parity-0 state frags + own flag
  { int idx = bid*NTHR + tid;
    if (idx < 16*BB*2){
      g_h0sF4[0][idx] = make_uint4(0,0,0,0);
      g_h1sF4[0][idx] = make_uint4(0,0,0,0);
    } }
  if (tid == 0) g_flags[bid*64] = 0u;

  unsigned base0 = 0;
  if (tid == 0) base0 = *(volatile unsigned*)&g_gen0;
  init_arrive_and_wait(base0);   // zeros + x frags + flags visible after

  float c0 = 0.f, c1 = 0.f, hk0 = 0.f, hk1 = 0.f;
  const int b1q = b1*4 + q, b2q = (b1+8)*4 + q;
  const int ktv = jg >> 4;
  const int fo  = fragoff(jg & 15);
  const uint2* wf = wfrag + wc*2048;

  for (int t = 0; t < TT; t++){
    float a0a[4]={0,0,0,0}, a0b[4]={0,0,0,0};
    float a1a[4]={0,0,0,0}, a1b[4]={0,0,0,0};

    if (layer == 0){
      // x half: no dependency — compute before any wait
      compute_frag((const uint2*)(g_xF4 + (size_t)t*16*128*2), wf, 0,
                   b1q, b2q, lane, a0a, a0b, a1a, a1b);
      if (t >= 1) wait_flags(own_g, (unsigned)t);        // own done t-1 (h0s)
      if (t >= 2) wait_flags(l1_g, (unsigned)(t-1));     // L1 done t-2 (h0n free)
      __syncthreads();
      compute_frag((const uint2*)g_h0sF4[t&1], wf, 16,
                   b1q, b2q, lane, a0a, a0b, a1a, a1b);
    } else {
      if (t >= 1) wait_flags(own_g, (unsigned)t);        // own done t-1 (h1s)
      __syncthreads();
      compute_frag((const uint2*)g_h1sF4[t&1], wf, 16,
                   b1q, b2q, lane, a0a, a0b, a1a, a1b);
      wait_flags(l0_g, (unsigned)(t+1));                 // L0 done t (h0n ready)
      __syncthreads();
      compute_frag((const uint2*)g_h0nF4[t&1], wf, 0,
                   b1q, b2q, lane, a0a, a0b, a1a, a1b);
    }

    float acc0[4], acc1[4];
    #pragma unroll
    for (int i = 0; i < 4; i++){ acc0[i] = a0a[i]+a0b[i]; acc1[i] = a1a[i]+a1b[i]; }

    // ---- in-register gate exchange + LSTM elementwise (R6 structure) ----
    {
      float s0 = __shfl_xor_sync(0xffffffffu, (q < 2) ? acc0[1] : acc0[0], 2);
      float s1 = __shfl_xor_sync(0xffffffffu, (q < 2) ? acc0[3] : acc0[2], 2);
      float s2 = __shfl_xor_sync(0xffffffffu, (q < 2) ? acc1[1] : acc1[0], 2);
      float s3 = __shfl_xor_sync(0xffffffffu, (q < 2) ? acc1[3] : acc1[2], 2);
      float gi0, gf0, gg0, go0, gi1, gf1, gg1, go1;
      if (q < 2){
        gi0 = acc0[0]; gf0 = s0; gg0 = acc1[0]; go0 = s2;
        gi1 = acc0[2]; gf1 = s1; gg1 = acc1[2]; go1 = s3;
      } else {
        gi0 = s0; gf0 = acc0[1]; gg0 = s2; go0 = acc1[1];
        gi1 = s1; gf1 = acc0[3]; gg1 = s3; go1 = acc1[3];
      }
      gi0 += biasv[0]; gf0 += biasv[1]; gg0 += biasv[2]; go0 += biasv[3];
      gi1 += biasv[0]; gf1 += biasv[1]; gg1 += biasv[2]; go1 += biasv[3];

      const int op0 = __ldg(ops + t*BB + b1);
      const int op1 = __ldg(ops + t*BB + b1 + 8);
      float cn0 = sigf(gf0)*c0 + sigf(gi0)*tanhf(gg0);
      float hn0 = sigf(go0)*tanhf(cn0);
      float cn1 = sigf(gf1)*c1 + sigf(gi1)*tanhf(gg1);
      float hn1 = sigf(go1)*tanhf(cn1);
      if (op0){ c0 = cn0; hk0 = hn0; }
      if (op1){ c1 = cn1; hk1 = hn1; }

      const int u0h = (ktv*128 + b1)*16 + fo;
      const int u1h = (ktv*128 + b1 + 8)*16 + fo;
      if (layer == 0){
        __half* fresh = (__half*)g_h0nF4[t&1];
        __half* keep  = (__half*)g_h0sF4[(t+1)&1];
        fresh[u0h] = __float2half_rn(hn0); fresh[u1h] = __float2half_rn(hn1);
        keep[u0h]  = __float2half_rn(hk0); keep[u1h]  = __float2half_rn(hk1);
      } else {
        float* fresh = out + t*BB*HH;
        __half* keep = (__half*)g_h1sF4[(t+1)&1];
        fresh[b1*HH + jg]     = hn0;
        fresh[(b1+8)*HH + jg] = hn1;
        keep[u0h]  = __float2half_rn(hk0); keep[u1h]  = __float2half_rn(hk1);
      }
    }

    __syncthreads();                               // all EW stores issued
    if (tid == 0) strel(&g_flags[bid*64], (unsigned)(t+1));
  }
}

extern "C" void kernel_launch(void* const* d_in, const int* in_sizes, int n_in,
                              void* d_out, int out_size)
{
  const float* x   = (const float*)d_in[0];
  const int*   ops = (const int*)  d_in[1];
  const float* Wih = (const float*)d_in[2];
  const float* Whh = (const float*)d_in[3];
  const float* bih = (const float*)d_in[4];
  const float* bhh = (const float*)d_in[5];
  float* out = (float*)d_out;
  stacklstm_h16<<<NBLK, NTHR>>>(x, ops, Wih, Whh, bih, bhh, out);
}